// round 5
// baseline (speedup 1.0000x reference)
#include <cuda_runtime.h>
#include <math.h>

// Branch-free fast tanh: 1 - 2/(1 + 2^(2*log2e*x)). Saturates correctly.
__device__ __forceinline__ float ftanh(float x) {
    float e;
    asm("ex2.approx.f32 %0, %1;" : "=f"(e) : "f"(x * 2.885390081777927f));
    float r;
    asm("rcp.approx.f32 %0, %1;" : "=f"(r) : "f"(e + 1.0f));
    return fmaf(-2.0f, r, 1.0f);
}

// Shared weight arena offsets (floats)
#define O_C1W 0
#define O_C1B 216
#define O_C2W 222
#define O_C2B 294
#define O_C3W 298
#define O_C3B 346
#define O_E1W 350
#define O_E1B 374
#define O_E2W 378
#define O_E2B 394
#define O_D1W 398
#define O_D1B 446
#define O_D2W 450
#define O_D2B 474
#define O_D3W 476
#define O_D3B 488
#define O_D4W 490
#define O_D4B 742
#define W_TOTAL 748

__global__ __launch_bounds__(128, 1)
void policy_kernel(const float* __restrict__ x,
                   const float* __restrict__ c1w, const float* __restrict__ c1b,
                   const float* __restrict__ c2w, const float* __restrict__ c2b,
                   const float* __restrict__ c3w, const float* __restrict__ c3b,
                   const float* __restrict__ e1w, const float* __restrict__ e1b,
                   const float* __restrict__ e2w, const float* __restrict__ e2b,
                   const float* __restrict__ d1w, const float* __restrict__ d1b,
                   const float* __restrict__ d2w, const float* __restrict__ d2b,
                   const float* __restrict__ d3w, const float* __restrict__ d3b,
                   const float* __restrict__ d4w, const float* __restrict__ d4b,
                   float* __restrict__ out)
{
    __shared__ float W[W_TOTAL];
    __shared__ float jcat[12][15];
    __shared__ float c1s[6][13];
    __shared__ float dss[6][5];
    __shared__ float c2s[4][3];
    __shared__ float embin[6];
    __shared__ float e1s[4];
    __shared__ float e2s[4];
    __shared__ float dc1[4][3];
    __shared__ float dc2[2][5];
    __shared__ float dc3[2][15];
    __shared__ float part[90];   // dec4 jcat-partials

    const int tid = threadIdx.x;

    // ==== Stage 0: prefetch all weights + build jcat (all 128 threads) ====
    #define CP(off, src, n) for (int i = tid; i < (n); i += 128) W[(off) + i] = src[i];
    CP(O_C1W, c1w, 216) CP(O_C1B, c1b, 6)
    CP(O_C2W, c2w, 72)  CP(O_C2B, c2b, 4)
    CP(O_C3W, c3w, 48)  CP(O_C3B, c3b, 4)
    CP(O_E1W, e1w, 24)  CP(O_E1B, e1b, 4)
    CP(O_E2W, e2w, 16)  CP(O_E2B, e2b, 4)
    CP(O_D1W, d1w, 48)  CP(O_D1B, d1b, 4)
    CP(O_D2W, d2w, 24)  CP(O_D2B, d2b, 2)
    CP(O_D3W, d3w, 12)  CP(O_D3B, d3b, 2)
    CP(O_D4W, d4w, 252) CP(O_D4B, d4b, 6)
    #undef CP

    for (int idx = tid; idx < 180; idx += 128) {
        int c = idx / 15, l = idx % 15;
        float v;
        if (c < 6) {
            int f = c * 15 + l;
            v = (f < 2) ? 0.f : x[f + 5];      // x[7 + (f-2)]
        } else {
            int f = (c - 6) * 15 + l;
            v = (f < 2) ? 0.f : x[f + 99];     // x[101 + (f-2)]
        }
        jcat[c][l] = v;
    }
    if (tid == 0) embin[5] = x[100];
    if (tid == 32) {   // psi in warp 1 -- atan2f divergence off warp 0's path
        float qw = x[3], qx = x[4], qy = x[5], qz = x[6];
        embin[4] = atan2f(qz, qw) - atan2f(-qx, qy);
    }
    __syncthreads();   // B1

    if (tid < 32) {
        // ======== WARP 0: full encoder/decoder chain, warp-synchronous ========
        const int lane = tid;

        // ---- conv1: (12,15)->(6,13), 4-way acc split ----
        for (int idx = lane; idx < 78; idx += 32) {
            int o = idx / 13, t = idx % 13;
            const float* w = &W[O_C1W + o * 36];
            float a0 = W[O_C1B + o], a1 = 0.f, a2 = 0.f, a3 = 0.f;
            #pragma unroll
            for (int j = 0; j < 3; j++) {
                a0 = fmaf(w[0*3+j], jcat[0][t+j], a0); a0 = fmaf(w[1*3+j], jcat[1][t+j], a0); a0 = fmaf(w[2*3+j],  jcat[2][t+j],  a0);
                a1 = fmaf(w[3*3+j], jcat[3][t+j], a1); a1 = fmaf(w[4*3+j], jcat[4][t+j], a1); a1 = fmaf(w[5*3+j],  jcat[5][t+j],  a1);
                a2 = fmaf(w[6*3+j], jcat[6][t+j], a2); a2 = fmaf(w[7*3+j], jcat[7][t+j], a2); a2 = fmaf(w[8*3+j],  jcat[8][t+j],  a2);
                a3 = fmaf(w[9*3+j], jcat[9][t+j], a3); a3 = fmaf(w[10*3+j],jcat[10][t+j],a3); a3 = fmaf(w[11*3+j], jcat[11][t+j], a3);
            }
            c1s[o][t] = ftanh((a0 + a1) + (a2 + a3));
        }
        __syncwarp();

        // ---- adaptive avg pool 13 -> 5 ----
        if (lane < 30) {
            int o = lane / 5, i = lane % 5;
            int s = (i * 13) / 5;
            int e = ((i + 1) * 13 + 4) / 5;
            float acc = 0.f;
            for (int l = s; l < e; l++) acc += c1s[o][l];
            dss[o][i] = acc / (float)(e - s);
        }
        __syncwarp();

        // ---- conv2: (6,5)->(4,3), 2-way acc ----
        if (lane < 12) {
            int o = lane / 3, t = lane % 3;
            const float* w = &W[O_C2W + o * 18];
            float a0 = W[O_C2B + o], a1 = 0.f;
            #pragma unroll
            for (int j = 0; j < 3; j++) {
                a0 = fmaf(w[0*3+j], dss[0][t+j], a0); a0 = fmaf(w[1*3+j], dss[1][t+j], a0); a0 = fmaf(w[2*3+j], dss[2][t+j], a0);
                a1 = fmaf(w[3*3+j], dss[3][t+j], a1); a1 = fmaf(w[4*3+j], dss[4][t+j], a1); a1 = fmaf(w[5*3+j], dss[5][t+j], a1);
            }
            c2s[o][t] = ftanh(a0 + a1);
        }
        __syncwarp();

        // ---- conv3: (4,3)->(4,1) ----
        if (lane < 4) {
            int o = lane;
            const float* w = &W[O_C3W + o * 12];
            float a0 = W[O_C3B + o], a1 = 0.f;
            #pragma unroll
            for (int j = 0; j < 3; j++) {
                a0 = fmaf(w[0*3+j], c2s[0][j], a0); a0 = fmaf(w[1*3+j], c2s[1][j], a0);
                a1 = fmaf(w[2*3+j], c2s[2][j], a1); a1 = fmaf(w[3*3+j], c2s[3][j], a1);
            }
            embin[o] = ftanh(a0 + a1);
        }
        __syncwarp();

        // ---- emb1: 1x1, 6->4 ----
        if (lane < 4) {
            int o = lane;
            float a0 = W[O_E1B + o], a1 = 0.f;
            a0 = fmaf(W[O_E1W + o*6 + 0], embin[0], a0);
            a0 = fmaf(W[O_E1W + o*6 + 1], embin[1], a0);
            a0 = fmaf(W[O_E1W + o*6 + 2], embin[2], a0);
            a1 = fmaf(W[O_E1W + o*6 + 3], embin[3], a1);
            a1 = fmaf(W[O_E1W + o*6 + 4], embin[4], a1);
            a1 = fmaf(W[O_E1W + o*6 + 5], embin[5], a1);
            e1s[o] = ftanh(a0 + a1);
        }
        __syncwarp();

        // ---- emb2: 1x1, 4->4 ----
        if (lane < 4) {
            int o = lane;
            float a0 = W[O_E2B + o], a1 = 0.f;
            a0 = fmaf(W[O_E2W + o*4 + 0], e1s[0], a0);
            a0 = fmaf(W[O_E2W + o*4 + 1], e1s[1], a0);
            a1 = fmaf(W[O_E2W + o*4 + 2], e1s[2], a1);
            a1 = fmaf(W[O_E2W + o*4 + 3], e1s[3], a1);
            e2s[o] = ftanh(a0 + a1);
        }
        __syncwarp();

        // ---- dec1 (convT, 4ch L1 -> 4ch L3) ----
        if (lane < 12) {
            int o = lane / 3, t = lane % 3;
            float a0 = W[O_D1B + o], a1 = 0.f;
            a0 = fmaf(W[O_D1W + 0*12 + o*3 + t], e2s[0], a0);
            a0 = fmaf(W[O_D1W + 1*12 + o*3 + t], e2s[1], a0);
            a1 = fmaf(W[O_D1W + 2*12 + o*3 + t], e2s[2], a1);
            a1 = fmaf(W[O_D1W + 3*12 + o*3 + t], e2s[3], a1);
            dc1[o][t] = ftanh(a0 + a1);
        }
        __syncwarp();

        // ---- dec2 (convT, 4ch L3 -> 2ch L5) ----
        if (lane < 10) {
            int o = lane / 5, t = lane % 5;
            float a0 = W[O_D2B + o], a1 = 0.f;
            #pragma unroll
            for (int m = 0; m < 3; m++) {
                int s = t - m;
                if (s >= 0 && s < 3) {
                    a0 = fmaf(W[O_D2W + 0*6 + o*3 + m], dc1[0][s], a0);
                    a0 = fmaf(W[O_D2W + 1*6 + o*3 + m], dc1[1][s], a0);
                    a1 = fmaf(W[O_D2W + 2*6 + o*3 + m], dc1[2][s], a1);
                    a1 = fmaf(W[O_D2W + 3*6 + o*3 + m], dc1[3][s], a1);
                }
            }
            dc2[o][t] = ftanh(a0 + a1);
        }
        __syncwarp();

        // ---- upsample(5->13) fused into dec3 (convT, 2ch L13 -> 2ch L15) ----
        if (lane < 30) {
            int o = lane / 15, t = lane % 15;
            const int UP[13] = {0,0,0,1,1,1,2,2,3,3,3,4,4};
            float a0 = W[O_D3B + o], a1 = 0.f;
            #pragma unroll
            for (int m = 0; m < 3; m++) {
                int s = t - m;
                if (s >= 0 && s < 13) {
                    a0 = fmaf(W[O_D3W + 0*6 + o*3 + m], dc2[0][UP[s]], a0);
                    a1 = fmaf(W[O_D3W + 1*6 + o*3 + m], dc2[1][UP[s]], a1);
                }
            }
            dc3[o][t] = ftanh(a0 + a1);
        }
    } else {
        // ======== WARPS 1-3: dec4 jcat-partials (channels 2..13), overlap ========
        int idx = tid - 32;
        if (idx < 90) {
            int o = idx / 15, t = idx % 15;
            float a0 = W[O_D4B + o], a1 = 0.f, a2 = 0.f;
            #pragma unroll
            for (int m = 0; m < 3; m++) {
                int s = t + 1 - m;
                if (s >= 0 && s < 15) {
                    a0 = fmaf(W[O_D4W + 2*18  + o*3 + m], jcat[0][s],  a0);
                    a0 = fmaf(W[O_D4W + 3*18  + o*3 + m], jcat[1][s],  a0);
                    a0 = fmaf(W[O_D4W + 4*18  + o*3 + m], jcat[2][s],  a0);
                    a0 = fmaf(W[O_D4W + 5*18  + o*3 + m], jcat[3][s],  a0);
                    a1 = fmaf(W[O_D4W + 6*18  + o*3 + m], jcat[4][s],  a1);
                    a1 = fmaf(W[O_D4W + 7*18  + o*3 + m], jcat[5][s],  a1);
                    a1 = fmaf(W[O_D4W + 8*18  + o*3 + m], jcat[6][s],  a1);
                    a1 = fmaf(W[O_D4W + 9*18  + o*3 + m], jcat[7][s],  a1);
                    a2 = fmaf(W[O_D4W + 10*18 + o*3 + m], jcat[8][s],  a2);
                    a2 = fmaf(W[O_D4W + 11*18 + o*3 + m], jcat[9][s],  a2);
                    a2 = fmaf(W[O_D4W + 12*18 + o*3 + m], jcat[10][s], a2);
                    a2 = fmaf(W[O_D4W + 13*18 + o*3 + m], jcat[11][s], a2);
                }
            }
            part[idx] = (a0 + a1) + a2;
        }
    }
    __syncthreads();   // B2

    // ==== dec4 final: add 2-channel dc3 contribution (6 FMAs) and store ====
    if (tid < 90) {
        int o = tid / 15, t = tid % 15;
        float acc = part[tid];
        #pragma unroll
        for (int m = 0; m < 3; m++) {
            int s = t + 1 - m;
            if (s >= 0 && s < 15) {
                acc = fmaf(W[O_D4W + 0*18 + o*3 + m], dc3[0][s], acc);
                acc = fmaf(W[O_D4W + 1*18 + o*3 + m], dc3[1][s], acc);
            }
        }
        if (tid >= 2) out[tid - 2] = acc;
    }
}

extern "C" void kernel_launch(void* const* d_in, const int* in_sizes, int n_in,
                              void* d_out, int out_size) {
    (void)in_sizes; (void)n_in; (void)out_size;
    policy_kernel<<<1, 128>>>(
        (const float*)d_in[0],
        (const float*)d_in[1],  (const float*)d_in[2],
        (const float*)d_in[3],  (const float*)d_in[4],
        (const float*)d_in[5],  (const float*)d_in[6],
        (const float*)d_in[7],  (const float*)d_in[8],
        (const float*)d_in[9],  (const float*)d_in[10],
        (const float*)d_in[11], (const float*)d_in[12],
        (const float*)d_in[13], (const float*)d_in[14],
        (const float*)d_in[15], (const float*)d_in[16],
        (const float*)d_in[17], (const float*)d_in[18],
        (float*)d_out);
}

// round 7
// speedup vs baseline: 1.0036x; 1.0036x over previous
#include <cuda_runtime.h>
#include <math.h>

// Branch-free fast tanh: 1 - 2/(1 + 2^(2*log2e*x)). Saturates correctly.
__device__ __forceinline__ float ftanh(float x) {
    float e;
    asm("ex2.approx.f32 %0, %1;" : "=f"(e) : "f"(x * 2.885390081777927f));
    float r;
    asm("rcp.approx.f32 %0, %1;" : "=f"(r) : "f"(e + 1.0f));
    return fmaf(-2.0f, r, 1.0f);
}

// Shared weight arena offsets (floats). c1w/d4w 16B-aligned for float4 loads.
#define O_C1W 0      // 216
#define O_D4W 216    // 252
#define O_C1B 468    // 6
#define O_C2W 474    // 72
#define O_C2B 546    // 4
#define O_C3W 550    // 48
#define O_C3B 598    // 4
#define O_E1W 602    // 24
#define O_E1B 626    // 4
#define O_E2W 630    // 16
#define O_E2B 646    // 4
#define O_D1W 650    // 48
#define O_D1B 698    // 4
#define O_D2W 702    // 24
#define O_D2B 726    // 2
#define O_D3W 728    // 12
#define O_D3B 740    // 2
#define O_D4B 742    // 6
#define W_TOTAL 748

__global__ __launch_bounds__(64, 1)
void policy_kernel(const float* __restrict__ x,
                   const float* __restrict__ c1w, const float* __restrict__ c1b,
                   const float* __restrict__ c2w, const float* __restrict__ c2b,
                   const float* __restrict__ c3w, const float* __restrict__ c3b,
                   const float* __restrict__ e1w, const float* __restrict__ e1b,
                   const float* __restrict__ e2w, const float* __restrict__ e2b,
                   const float* __restrict__ d1w, const float* __restrict__ d1b,
                   const float* __restrict__ d2w, const float* __restrict__ d2b,
                   const float* __restrict__ d3w, const float* __restrict__ d3b,
                   const float* __restrict__ d4w, const float* __restrict__ d4b,
                   float* __restrict__ out)
{
    __shared__ __align__(16) float W[W_TOTAL];
    __shared__ float jcat[12][15];
    __shared__ float c1s[6][13];
    __shared__ float dss[6][5];
    __shared__ float c2s[4][3];
    __shared__ float embin[6];
    __shared__ float e1s[4];
    __shared__ float e2s[4];
    __shared__ float dc1[4][3];
    __shared__ float dc2[2][5];
    __shared__ float dc3[2][15];
    __shared__ float part[90];   // dec4 jcat-partials

    const int tid = threadIdx.x;

    // ==== Stage 0: prefetch weights (vectorized for the two big arrays) ====
    if (tid < 54) ((float4*)&W[O_C1W])[tid] = ((const float4*)c1w)[tid];
    if (tid < 63) ((float4*)&W[O_D4W])[tid] = ((const float4*)d4w)[tid];
    #define CP(off, src, n) for (int i = tid; i < (n); i += 64) W[(off) + i] = src[i];
    CP(O_C1B, c1b, 6)
    CP(O_C2W, c2w, 72)  CP(O_C2B, c2b, 4)
    CP(O_C3W, c3w, 48)  CP(O_C3B, c3b, 4)
    CP(O_E1W, e1w, 24)  CP(O_E1B, e1b, 4)
    CP(O_E2W, e2w, 16)  CP(O_E2B, e2b, 4)
    CP(O_D1W, d1w, 48)  CP(O_D1B, d1b, 4)
    CP(O_D2W, d2w, 24)  CP(O_D2B, d2b, 2)
    CP(O_D3W, d3w, 12)  CP(O_D3B, d3b, 2)
    CP(O_D4B, d4b, 6)
    #undef CP

    for (int idx = tid; idx < 180; idx += 64) {
        int c = idx / 15, l = idx % 15;
        float v;
        if (c < 6) {
            int f = c * 15 + l;
            v = (f < 2) ? 0.f : x[f + 5];      // x[7 + (f-2)]
        } else {
            int f = (c - 6) * 15 + l;
            v = (f < 2) ? 0.f : x[f + 99];     // x[101 + (f-2)]
        }
        jcat[c][l] = v;
    }
    if (tid == 0) embin[5] = x[100];
    if (tid == 32) {   // psi in warp 1 -- atan2f divergence off warp 0's path
        float qw = x[3], qx = x[4], qy = x[5], qz = x[6];
        embin[4] = atan2f(qz, qw) - atan2f(-qx, qy);
    }
    __syncthreads();   // B1

    if (tid < 32) {
        // ======== WARP 0: full encoder/decoder chain, warp-synchronous ========
        const int lane = tid;

        // ---- conv1: (12,15)->(6,13), 4-way acc split ----
        for (int idx = lane; idx < 78; idx += 32) {
            int o = idx / 13, t = idx % 13;
            const float* w = &W[O_C1W + o * 36];
            float a0 = W[O_C1B + o], a1 = 0.f, a2 = 0.f, a3 = 0.f;
            #pragma unroll
            for (int j = 0; j < 3; j++) {
                a0 = fmaf(w[0*3+j], jcat[0][t+j], a0); a0 = fmaf(w[1*3+j], jcat[1][t+j], a0); a0 = fmaf(w[2*3+j],  jcat[2][t+j],  a0);
                a1 = fmaf(w[3*3+j], jcat[3][t+j], a1); a1 = fmaf(w[4*3+j], jcat[4][t+j], a1); a1 = fmaf(w[5*3+j],  jcat[5][t+j],  a1);
                a2 = fmaf(w[6*3+j], jcat[6][t+j], a2); a2 = fmaf(w[7*3+j], jcat[7][t+j], a2); a2 = fmaf(w[8*3+j],  jcat[8][t+j],  a2);
                a3 = fmaf(w[9*3+j], jcat[9][t+j], a3); a3 = fmaf(w[10*3+j],jcat[10][t+j],a3); a3 = fmaf(w[11*3+j], jcat[11][t+j], a3);
            }
            c1s[o][t] = ftanh((a0 + a1) + (a2 + a3));
        }
        __syncwarp();

        // ---- adaptive avg pool 13 -> 5 ----
        if (lane < 30) {
            int o = lane / 5, i = lane % 5;
            int s = (i * 13) / 5;
            int e = ((i + 1) * 13 + 4) / 5;
            float acc = 0.f;
            for (int l = s; l < e; l++) acc += c1s[o][l];
            dss[o][i] = acc / (float)(e - s);
        }
        __syncwarp();

        // ---- conv2: (6,5)->(4,3), 2-way acc ----
        if (lane < 12) {
            int o = lane / 3, t = lane % 3;
            const float* w = &W[O_C2W + o * 18];
            float a0 = W[O_C2B + o], a1 = 0.f;
            #pragma unroll
            for (int j = 0; j < 3; j++) {
                a0 = fmaf(w[0*3+j], dss[0][t+j], a0); a0 = fmaf(w[1*3+j], dss[1][t+j], a0); a0 = fmaf(w[2*3+j], dss[2][t+j], a0);
                a1 = fmaf(w[3*3+j], dss[3][t+j], a1); a1 = fmaf(w[4*3+j], dss[4][t+j], a1); a1 = fmaf(w[5*3+j], dss[5][t+j], a1);
            }
            c2s[o][t] = ftanh(a0 + a1);
        }
        __syncwarp();

        // ---- conv3: (4,3)->(4,1) ----
        if (lane < 4) {
            int o = lane;
            const float* w = &W[O_C3W + o * 12];
            float a0 = W[O_C3B + o], a1 = 0.f;
            #pragma unroll
            for (int j = 0; j < 3; j++) {
                a0 = fmaf(w[0*3+j], c2s[0][j], a0); a0 = fmaf(w[1*3+j], c2s[1][j], a0);
                a1 = fmaf(w[2*3+j], c2s[2][j], a1); a1 = fmaf(w[3*3+j], c2s[3][j], a1);
            }
            embin[o] = ftanh(a0 + a1);
        }
        __syncwarp();

        // ---- emb1: 1x1, 6->4 ----
        if (lane < 4) {
            int o = lane;
            float a0 = W[O_E1B + o], a1 = 0.f;
            a0 = fmaf(W[O_E1W + o*6 + 0], embin[0], a0);
            a0 = fmaf(W[O_E1W + o*6 + 1], embin[1], a0);
            a0 = fmaf(W[O_E1W + o*6 + 2], embin[2], a0);
            a1 = fmaf(W[O_E1W + o*6 + 3], embin[3], a1);
            a1 = fmaf(W[O_E1W + o*6 + 4], embin[4], a1);
            a1 = fmaf(W[O_E1W + o*6 + 5], embin[5], a1);
            e1s[o] = ftanh(a0 + a1);
        }
        __syncwarp();

        // ---- emb2: 1x1, 4->4 ----
        if (lane < 4) {
            int o = lane;
            float a0 = W[O_E2B + o], a1 = 0.f;
            a0 = fmaf(W[O_E2W + o*4 + 0], e1s[0], a0);
            a0 = fmaf(W[O_E2W + o*4 + 1], e1s[1], a0);
            a1 = fmaf(W[O_E2W + o*4 + 2], e1s[2], a1);
            a1 = fmaf(W[O_E2W + o*4 + 3], e1s[3], a1);
            e2s[o] = ftanh(a0 + a1);
        }
        __syncwarp();

        // ---- dec1 (convT, 4ch L1 -> 4ch L3) ----
        if (lane < 12) {
            int o = lane / 3, t = lane % 3;
            float a0 = W[O_D1B + o], a1 = 0.f;
            a0 = fmaf(W[O_D1W + 0*12 + o*3 + t], e2s[0], a0);
            a0 = fmaf(W[O_D1W + 1*12 + o*3 + t], e2s[1], a0);
            a1 = fmaf(W[O_D1W + 2*12 + o*3 + t], e2s[2], a1);
            a1 = fmaf(W[O_D1W + 3*12 + o*3 + t], e2s[3], a1);
            dc1[o][t] = ftanh(a0 + a1);
        }
        __syncwarp();

        // ---- dec2 (convT, 4ch L3 -> 2ch L5) ----
        if (lane < 10) {
            int o = lane / 5, t = lane % 5;
            float a0 = W[O_D2B + o], a1 = 0.f;
            #pragma unroll
            for (int m = 0; m < 3; m++) {
                int s = t - m;
                if (s >= 0 && s < 3) {
                    a0 = fmaf(W[O_D2W + 0*6 + o*3 + m], dc1[0][s], a0);
                    a0 = fmaf(W[O_D2W + 1*6 + o*3 + m], dc1[1][s], a0);
                    a1 = fmaf(W[O_D2W + 2*6 + o*3 + m], dc1[2][s], a1);
                    a1 = fmaf(W[O_D2W + 3*6 + o*3 + m], dc1[3][s], a1);
                }
            }
            dc2[o][t] = ftanh(a0 + a1);
        }
        __syncwarp();

        // ---- upsample(5->13) fused into dec3 (convT, 2ch L13 -> 2ch L15) ----
        if (lane < 30) {
            int o = lane / 15, t = lane % 15;
            const int UP[13] = {0,0,0,1,1,1,2,2,3,3,3,4,4};
            float a0 = W[O_D3B + o], a1 = 0.f;
            #pragma unroll
            for (int m = 0; m < 3; m++) {
                int s = t - m;
                if (s >= 0 && s < 13) {
                    a0 = fmaf(W[O_D3W + 0*6 + o*3 + m], dc2[0][UP[s]], a0);
                    a1 = fmaf(W[O_D3W + 1*6 + o*3 + m], dc2[1][UP[s]], a1);
                }
            }
            dc3[o][t] = ftanh(a0 + a1);
        }
    } else {
        // ======== WARP 1: dec4 jcat-partials (channels 2..13), overlapped ========
        for (int idx = tid - 32; idx < 90; idx += 32) {
            int o = idx / 15, t = idx % 15;
            float a0 = W[O_D4B + o], a1 = 0.f, a2 = 0.f;
            #pragma unroll
            for (int m = 0; m < 3; m++) {
                int s = t + 1 - m;
                if (s >= 0 && s < 15) {
                    a0 = fmaf(W[O_D4W + 2*18  + o*3 + m], jcat[0][s],  a0);
                    a0 = fmaf(W[O_D4W + 3*18  + o*3 + m], jcat[1][s],  a0);
                    a0 = fmaf(W[O_D4W + 4*18  + o*3 + m], jcat[2][s],  a0);
                    a0 = fmaf(W[O_D4W + 5*18  + o*3 + m], jcat[3][s],  a0);
                    a1 = fmaf(W[O_D4W + 6*18  + o*3 + m], jcat[4][s],  a1);
                    a1 = fmaf(W[O_D4W + 7*18  + o*3 + m], jcat[5][s],  a1);
                    a1 = fmaf(W[O_D4W + 8*18  + o*3 + m], jcat[6][s],  a1);
                    a1 = fmaf(W[O_D4W + 9*18  + o*3 + m], jcat[7][s],  a1);
                    a2 = fmaf(W[O_D4W + 10*18 + o*3 + m], jcat[8][s],  a2);
                    a2 = fmaf(W[O_D4W + 11*18 + o*3 + m], jcat[9][s],  a2);
                    a2 = fmaf(W[O_D4W + 12*18 + o*3 + m], jcat[10][s], a2);
                    a2 = fmaf(W[O_D4W + 13*18 + o*3 + m], jcat[11][s], a2);
                }
            }
            part[idx] = (a0 + a1) + a2;
        }
    }
    __syncthreads();   // B2

    // ==== dec4 final: add 2-channel dc3 contribution (6 FMAs) and store ====
    for (int idx = tid; idx < 90; idx += 64) {
        int o = idx / 15, t = idx % 15;
        float acc = part[idx];
        #pragma unroll
        for (int m = 0; m < 3; m++) {
            int s = t + 1 - m;
            if (s >= 0 && s < 15) {
                acc = fmaf(W[O_D4W + 0*18 + o*3 + m], dc3[0][s], acc);
                acc = fmaf(W[O_D4W + 1*18 + o*3 + m], dc3[1][s], acc);
            }
        }
        if (idx >= 2) out[idx - 2] = acc;
    }
}

extern "C" void kernel_launch(void* const* d_in, const int* in_sizes, int n_in,
                              void* d_out, int out_size) {
    (void)in_sizes; (void)n_in; (void)out_size;
    policy_kernel<<<1, 64>>>(
        (const float*)d_in[0],
        (const float*)d_in[1],  (const float*)d_in[2],
        (const float*)d_in[3],  (const float*)d_in[4],
        (const float*)d_in[5],  (const float*)d_in[6],
        (const float*)d_in[7],  (const float*)d_in[8],
        (const float*)d_in[9],  (const float*)d_in[10],
        (const float*)d_in[11], (const float*)d_in[12],
        (const float*)d_in[13], (const float*)d_in[14],
        (const float*)d_in[15], (const float*)d_in[16],
        (const float*)d_in[17], (const float*)d_in[18],
        (float*)d_out);
}

// round 8
// speedup vs baseline: 1.0294x; 1.0257x over previous
#include <cuda_runtime.h>
#include <math.h>

// Branch-free fast tanh: 1 - 2/(1 + 2^(2*log2e*x)). Saturates correctly.
__device__ __forceinline__ float ftanh(float x) {
    float e;
    asm("ex2.approx.f32 %0, %1;" : "=f"(e) : "f"(x * 2.885390081777927f));
    float r;
    asm("rcp.approx.f32 %0, %1;" : "=f"(r) : "f"(e + 1.0f));
    return fmaf(-2.0f, r, 1.0f);
}

// Branch-free fast atan2, abs err ~1e-4 rad (plenty: output tolerance 1e-3,
// psi enters through a ~0.1-magnitude weight).
__device__ __forceinline__ float fatan2(float y, float x) {
    float ax = fabsf(x), ay = fabsf(y);
    float mn = fminf(ax, ay), mx = fmaxf(ax, ay);
    float r;
    asm("rcp.approx.f32 %0, %1;" : "=f"(r) : "f"(mx));
    float t = mn * r;          // in [0,1]
    float s = t * t;
    float p = fmaf(s, fmaf(s, fmaf(s, fmaf(s, 0.0208351f, -0.085133f),
                                   0.180141f), -0.3302995f), 0.999866f);
    float a = t * p;           // atan(mn/mx) in [0, pi/4]
    a = (ay > ax) ? (1.57079632679f - a) : a;
    a = (x < 0.f) ? (3.14159265359f - a) : a;
    return (y < 0.f) ? -a : a;
}

// Shared weight arena offsets (floats). c1w/d4w 16B-aligned for float4 loads.
#define O_C1W 0      // 216
#define O_D4W 216    // 252
#define O_C1B 468    // 6
#define O_C2W 474    // 72
#define O_C2B 546    // 4
#define O_C3W 550    // 48
#define O_C3B 598    // 4
#define O_E1W 602    // 24
#define O_E1B 626    // 4
#define O_E2W 630    // 16
#define O_E2B 646    // 4
#define O_D1W 650    // 48
#define O_D1B 698    // 4
#define O_D2W 702    // 24
#define O_D2B 726    // 2
#define O_D3W 728    // 12
#define O_D3B 740    // 2
#define O_D4B 742    // 6
#define W_TOTAL 748

__global__ __launch_bounds__(128, 1)
void policy_kernel(const float* __restrict__ x,
                   const float* __restrict__ c1w, const float* __restrict__ c1b,
                   const float* __restrict__ c2w, const float* __restrict__ c2b,
                   const float* __restrict__ c3w, const float* __restrict__ c3b,
                   const float* __restrict__ e1w, const float* __restrict__ e1b,
                   const float* __restrict__ e2w, const float* __restrict__ e2b,
                   const float* __restrict__ d1w, const float* __restrict__ d1b,
                   const float* __restrict__ d2w, const float* __restrict__ d2b,
                   const float* __restrict__ d3w, const float* __restrict__ d3b,
                   const float* __restrict__ d4w, const float* __restrict__ d4b,
                   float* __restrict__ out)
{
    __shared__ __align__(16) float W[W_TOTAL];
    __shared__ float jcat[12][15];
    __shared__ float c1s[6][13];
    __shared__ float dss[6][5];
    __shared__ float c2s[4][3];
    __shared__ float embin[6];
    __shared__ float e1s[4];
    __shared__ float e2s[4];
    __shared__ float dc1[4][3];
    __shared__ float dc2[2][5];
    __shared__ float dc3[2][15];
    __shared__ float part[90];   // dec4 jcat-partials

    const int tid = threadIdx.x;

    // ==== Stage 0: prefetch weights + build jcat. Lane 31 issues psi-input
    //      loads into registers (psi itself computed AFTER B1, off the chain).
    float qw_r = 0.f, qx_r = 0.f, qy_r = 0.f, qz_r = 0.f, x100_r = 0.f;
    if (tid == 31) {
        qw_r = x[3]; qx_r = x[4]; qy_r = x[5]; qz_r = x[6]; x100_r = x[100];
    }

    if (tid < 54) ((float4*)&W[O_C1W])[tid] = ((const float4*)c1w)[tid];
    if (tid < 63) ((float4*)&W[O_D4W])[tid] = ((const float4*)d4w)[tid];
    #define CP(off, src, n) for (int i = tid; i < (n); i += 128) W[(off) + i] = src[i];
    CP(O_C1B, c1b, 6)
    CP(O_C2W, c2w, 72)  CP(O_C2B, c2b, 4)
    CP(O_C3W, c3w, 48)  CP(O_C3B, c3b, 4)
    CP(O_E1W, e1w, 24)  CP(O_E1B, e1b, 4)
    CP(O_E2W, e2w, 16)  CP(O_E2B, e2b, 4)
    CP(O_D1W, d1w, 48)  CP(O_D1B, d1b, 4)
    CP(O_D2W, d2w, 24)  CP(O_D2B, d2b, 2)
    CP(O_D3W, d3w, 12)  CP(O_D3B, d3b, 2)
    CP(O_D4B, d4b, 6)
    #undef CP

    for (int idx = tid; idx < 180; idx += 128) {
        int c = idx / 15, l = idx % 15;
        float v;
        if (c < 6) {
            int f = c * 15 + l;
            v = (f < 2) ? 0.f : x[f + 5];      // x[7 + (f-2)]
        } else {
            int f = (c - 6) * 15 + l;
            v = (f < 2) ? 0.f : x[f + 99];     // x[101 + (f-2)]
        }
        jcat[c][l] = v;
    }
    __syncthreads();   // B1

    if (tid < 32) {
        // ======== WARP 0: full encoder/decoder chain, warp-synchronous ========
        const int lane = tid;

        // ---- psi on lane 31 (has conv1 slack; needed only at emb1, 4 syncwarps later)
        if (lane == 31) {
            embin[4] = fatan2(qz_r, qw_r) - fatan2(-qx_r, qy_r);
            embin[5] = x100_r;
        }

        // ---- conv1: (12,15)->(6,13), 4-way acc split ----
        for (int idx = lane; idx < 78; idx += 32) {
            int o = idx / 13, t = idx % 13;
            const float* w = &W[O_C1W + o * 36];
            float a0 = W[O_C1B + o], a1 = 0.f, a2 = 0.f, a3 = 0.f;
            #pragma unroll
            for (int j = 0; j < 3; j++) {
                a0 = fmaf(w[0*3+j], jcat[0][t+j], a0); a0 = fmaf(w[1*3+j], jcat[1][t+j], a0); a0 = fmaf(w[2*3+j],  jcat[2][t+j],  a0);
                a1 = fmaf(w[3*3+j], jcat[3][t+j], a1); a1 = fmaf(w[4*3+j], jcat[4][t+j], a1); a1 = fmaf(w[5*3+j],  jcat[5][t+j],  a1);
                a2 = fmaf(w[6*3+j], jcat[6][t+j], a2); a2 = fmaf(w[7*3+j], jcat[7][t+j], a2); a2 = fmaf(w[8*3+j],  jcat[8][t+j],  a2);
                a3 = fmaf(w[9*3+j], jcat[9][t+j], a3); a3 = fmaf(w[10*3+j],jcat[10][t+j],a3); a3 = fmaf(w[11*3+j], jcat[11][t+j], a3);
            }
            c1s[o][t] = ftanh((a0 + a1) + (a2 + a3));
        }
        __syncwarp();

        // ---- adaptive avg pool 13 -> 5 ----
        if (lane < 30) {
            int o = lane / 5, i = lane % 5;
            int s = (i * 13) / 5;
            int e = ((i + 1) * 13 + 4) / 5;
            float acc = 0.f;
            for (int l = s; l < e; l++) acc += c1s[o][l];
            dss[o][i] = acc / (float)(e - s);
        }
        __syncwarp();

        // ---- conv2: (6,5)->(4,3), 2-way acc ----
        if (lane < 12) {
            int o = lane / 3, t = lane % 3;
            const float* w = &W[O_C2W + o * 18];
            float a0 = W[O_C2B + o], a1 = 0.f;
            #pragma unroll
            for (int j = 0; j < 3; j++) {
                a0 = fmaf(w[0*3+j], dss[0][t+j], a0); a0 = fmaf(w[1*3+j], dss[1][t+j], a0); a0 = fmaf(w[2*3+j], dss[2][t+j], a0);
                a1 = fmaf(w[3*3+j], dss[3][t+j], a1); a1 = fmaf(w[4*3+j], dss[4][t+j], a1); a1 = fmaf(w[5*3+j], dss[5][t+j], a1);
            }
            c2s[o][t] = ftanh(a0 + a1);
        }
        __syncwarp();

        // ---- conv3: (4,3)->(4,1) ----
        if (lane < 4) {
            int o = lane;
            const float* w = &W[O_C3W + o * 12];
            float a0 = W[O_C3B + o], a1 = 0.f;
            #pragma unroll
            for (int j = 0; j < 3; j++) {
                a0 = fmaf(w[0*3+j], c2s[0][j], a0); a0 = fmaf(w[1*3+j], c2s[1][j], a0);
                a1 = fmaf(w[2*3+j], c2s[2][j], a1); a1 = fmaf(w[3*3+j], c2s[3][j], a1);
            }
            embin[o] = ftanh(a0 + a1);
        }
        __syncwarp();

        // ---- emb1: 1x1, 6->4 ----
        if (lane < 4) {
            int o = lane;
            float a0 = W[O_E1B + o], a1 = 0.f;
            a0 = fmaf(W[O_E1W + o*6 + 0], embin[0], a0);
            a0 = fmaf(W[O_E1W + o*6 + 1], embin[1], a0);
            a0 = fmaf(W[O_E1W + o*6 + 2], embin[2], a0);
            a1 = fmaf(W[O_E1W + o*6 + 3], embin[3], a1);
            a1 = fmaf(W[O_E1W + o*6 + 4], embin[4], a1);
            a1 = fmaf(W[O_E1W + o*6 + 5], embin[5], a1);
            e1s[o] = ftanh(a0 + a1);
        }
        __syncwarp();

        // ---- emb2: 1x1, 4->4 ----
        if (lane < 4) {
            int o = lane;
            float a0 = W[O_E2B + o], a1 = 0.f;
            a0 = fmaf(W[O_E2W + o*4 + 0], e1s[0], a0);
            a0 = fmaf(W[O_E2W + o*4 + 1], e1s[1], a0);
            a1 = fmaf(W[O_E2W + o*4 + 2], e1s[2], a1);
            a1 = fmaf(W[O_E2W + o*4 + 3], e1s[3], a1);
            e2s[o] = ftanh(a0 + a1);
        }
        __syncwarp();

        // ---- dec1 (convT, 4ch L1 -> 4ch L3) ----
        if (lane < 12) {
            int o = lane / 3, t = lane % 3;
            float a0 = W[O_D1B + o], a1 = 0.f;
            a0 = fmaf(W[O_D1W + 0*12 + o*3 + t], e2s[0], a0);
            a0 = fmaf(W[O_D1W + 1*12 + o*3 + t], e2s[1], a0);
            a1 = fmaf(W[O_D1W + 2*12 + o*3 + t], e2s[2], a1);
            a1 = fmaf(W[O_D1W + 3*12 + o*3 + t], e2s[3], a1);
            dc1[o][t] = ftanh(a0 + a1);
        }
        __syncwarp();

        // ---- dec2 (convT, 4ch L3 -> 2ch L5) ----
        if (lane < 10) {
            int o = lane / 5, t = lane % 5;
            float a0 = W[O_D2B + o], a1 = 0.f;
            #pragma unroll
            for (int m = 0; m < 3; m++) {
                int s = t - m;
                if (s >= 0 && s < 3) {
                    a0 = fmaf(W[O_D2W + 0*6 + o*3 + m], dc1[0][s], a0);
                    a0 = fmaf(W[O_D2W + 1*6 + o*3 + m], dc1[1][s], a0);
                    a1 = fmaf(W[O_D2W + 2*6 + o*3 + m], dc1[2][s], a1);
                    a1 = fmaf(W[O_D2W + 3*6 + o*3 + m], dc1[3][s], a1);
                }
            }
            dc2[o][t] = ftanh(a0 + a1);
        }
        __syncwarp();

        // ---- upsample(5->13) fused into dec3 (convT, 2ch L13 -> 2ch L15) ----
        if (lane < 30) {
            int o = lane / 15, t = lane % 15;
            const int UP[13] = {0,0,0,1,1,1,2,2,3,3,3,4,4};
            float a0 = W[O_D3B + o], a1 = 0.f;
            #pragma unroll
            for (int m = 0; m < 3; m++) {
                int s = t - m;
                if (s >= 0 && s < 13) {
                    a0 = fmaf(W[O_D3W + 0*6 + o*3 + m], dc2[0][UP[s]], a0);
                    a1 = fmaf(W[O_D3W + 1*6 + o*3 + m], dc2[1][UP[s]], a1);
                }
            }
            dc3[o][t] = ftanh(a0 + a1);
        }
    } else if (tid < 122) {
        // ======== WARPS 1-3: dec4 jcat-partials (channels 2..13), one each ====
        int idx = tid - 32;
        int o = idx / 15, t = idx % 15;
        float a0 = W[O_D4B + o], a1 = 0.f, a2 = 0.f;
        #pragma unroll
        for (int m = 0; m < 3; m++) {
            int s = t + 1 - m;
            if (s >= 0 && s < 15) {
                a0 = fmaf(W[O_D4W + 2*18  + o*3 + m], jcat[0][s],  a0);
                a0 = fmaf(W[O_D4W + 3*18  + o*3 + m], jcat[1][s],  a0);
                a0 = fmaf(W[O_D4W + 4*18  + o*3 + m], jcat[2][s],  a0);
                a0 = fmaf(W[O_D4W + 5*18  + o*3 + m], jcat[3][s],  a0);
                a1 = fmaf(W[O_D4W + 6*18  + o*3 + m], jcat[4][s],  a1);
                a1 = fmaf(W[O_D4W + 7*18  + o*3 + m], jcat[5][s],  a1);
                a1 = fmaf(W[O_D4W + 8*18  + o*3 + m], jcat[6][s],  a1);
                a1 = fmaf(W[O_D4W + 9*18  + o*3 + m], jcat[7][s],  a1);
                a2 = fmaf(W[O_D4W + 10*18 + o*3 + m], jcat[8][s],  a2);
                a2 = fmaf(W[O_D4W + 11*18 + o*3 + m], jcat[9][s],  a2);
                a2 = fmaf(W[O_D4W + 12*18 + o*3 + m], jcat[10][s], a2);
                a2 = fmaf(W[O_D4W + 13*18 + o*3 + m], jcat[11][s], a2);
            }
        }
        part[idx] = (a0 + a1) + a2;
    }
    __syncthreads();   // B2

    // ==== dec4 final: add 2-channel dc3 contribution (6 FMAs) and store ====
    if (tid < 90) {
        int o = tid / 15, t = tid % 15;
        float acc = part[tid];
        #pragma unroll
        for (int m = 0; m < 3; m++) {
            int s = t + 1 - m;
            if (s >= 0 && s < 15) {
                acc = fmaf(W[O_D4W + 0*18 + o*3 + m], dc3[0][s], acc);
                acc = fmaf(W[O_D4W + 1*18 + o*3 + m], dc3[1][s], acc);
            }
        }
        if (tid >= 2) out[tid - 2] = acc;
    }
}

extern "C" void kernel_launch(void* const* d_in, const int* in_sizes, int n_in,
                              void* d_out, int out_size) {
    (void)in_sizes; (void)n_in; (void)out_size;
    policy_kernel<<<1, 128>>>(
        (const float*)d_in[0],
        (const float*)d_in[1],  (const float*)d_in[2],
        (const float*)d_in[3],  (const float*)d_in[4],
        (const float*)d_in[5],  (const float*)d_in[6],
        (const float*)d_in[7],  (const float*)d_in[8],
        (const float*)d_in[9],  (const float*)d_in[10],
        (const float*)d_in[11], (const float*)d_in[12],
        (const float*)d_in[13], (const float*)d_in[14],
        (const float*)d_in[15], (const float*)d_in[16],
        (const float*)d_in[17], (const float*)d_in[18],
        (float*)d_out);
}